// round 1
// baseline (speedup 1.0000x reference)
#include <cuda_runtime.h>
#include <cuda_fp16.h>

#define MAXN 8192
#define HD 64

// ---------------- static device scratch (no allocations allowed) ----------------
__device__ float g_WzT[HD * HD];
__device__ float g_WrT[HD * HD];
__device__ float g_WhT[HD * HD];
__device__ float g_az[MAXN * HD];
__device__ float g_ar[MAXN * HD];
__device__ float g_ah[MAXN * HD];
__device__ float g_h[MAXN * HD];
__device__ int g_dep[MAXN];
__device__ int g_wr[MAXN];
__device__ volatile int g_ready[MAXN];
__device__ unsigned g_max[HD];

// ---------------- prep: transpose W matrices, compact write-index array, reset flags ----------------
__global__ void prep_kernel(const float* __restrict__ Wz, const float* __restrict__ Wr,
                            const float* __restrict__ Wh, const int* __restrict__ tree,
                            int n_steps) {
    int t = blockIdx.x * blockDim.x + threadIdx.x;
    if (t < HD * HD) {
        int j = t / HD, k = t % HD;
        g_WzT[k * HD + j] = Wz[t];
        g_WrT[k * HD + j] = Wr[t];
        g_WhT[k * HD + j] = Wh[t];
    }
    if (t < n_steps) {
        g_wr[t] = tree[2 * t + 1];
        g_ready[t] = 0;
    }
    if (t < HD) g_max[t] = 0u;
}

// ---------------- dep(i) = last j<i with tree[j,1] == tree[i,0], else -1 ----------------
__global__ void dep_kernel(const int* __restrict__ tree, int n_steps) {
    int i = blockIdx.x * blockDim.x + threadIdx.x;
    if (i >= n_steps) return;
    int v = tree[2 * i];
    int d = -1;
    for (int j = i - 1; j >= 0; --j) {
        if (g_wr[j] == v) { d = j; break; }
    }
    g_dep[i] = d;
}

// ---------------- gather: xe[i] = sum_l w[i,l]*emb[idx[i,l]], then a_* = W_* @ xe + b_* ----------------
__global__ void gather_kernel(const float* __restrict__ xw, const int* __restrict__ xi,
                              const float* __restrict__ emb,
                              const float* __restrict__ bz, const float* __restrict__ br,
                              const float* __restrict__ bh, int L) {
    int i = blockIdx.x;      // step index
    int tid = threadIdx.x;   // 0..63 = output dim
    __shared__ float ws[512];
    __shared__ int is_[512];
    __shared__ float xe_s[HD];

    const float* xwrow = xw + (size_t)i * L;
    const int* xirow = xi + (size_t)i * L;

    float acc = 0.f;
    for (int base = 0; base < L; base += 512) {
        int chunk = min(512, L - base);
        __syncthreads();
        for (int l = tid; l < chunk; l += HD) {
            ws[l] = xwrow[base + l];
            is_[l] = xirow[base + l];
        }
        __syncthreads();
        int l = 0;
        for (; l + 8 <= chunk; l += 8) {
            int r[8];
            float v[8];
#pragma unroll
            for (int u = 0; u < 8; u++) r[u] = is_[l + u];
#pragma unroll
            for (int u = 0; u < 8; u++) v[u] = __ldg(&emb[(size_t)r[u] * HD + tid]);
#pragma unroll
            for (int u = 0; u < 8; u++) acc = fmaf(ws[l + u], v[u], acc);
        }
        for (; l < chunk; l++)
            acc = fmaf(ws[l], __ldg(&emb[(size_t)is_[l] * HD + tid]), acc);
    }

    xe_s[tid] = acc;
    __syncthreads();

    float az = bz[tid], ar = br[tid], ah = bh[tid];
#pragma unroll 8
    for (int k = 0; k < HD; k++) {
        float x = xe_s[k];
        az = fmaf(g_WzT[k * HD + tid], x, az);
        ar = fmaf(g_WrT[k * HD + tid], x, ar);
        ah = fmaf(g_WhT[k * HD + tid], x, ah);
    }
    g_az[(size_t)i * HD + tid] = az;
    g_ar[(size_t)i * HD + tid] = ar;
    g_ah[(size_t)i * HD + tid] = ah;
}

// ---------------- dataflow recurrence: h_i = f(h_{dep(i)}, a_*[i]) ----------------
__global__ void __launch_bounds__(256, 2)
recur_kernel(const float* __restrict__ Uz, const float* __restrict__ Ur,
             const float* __restrict__ Uh, const int* __restrict__ np_ptr, int n_steps) {
    int tid = threadIdx.x;
    int w = tid >> 5, l = tid & 31;
    int j = w * 8 + (l >> 2);  // output dim 0..63
    int k0 = (l & 3) * 16;     // this lane's k-chunk
    bool leader = (l & 3) == 0;

    float uz[16], ur[16], uh[16];
#pragma unroll
    for (int u = 0; u < 16; u++) {
        uz[u] = Uz[j * HD + k0 + u];
        ur[u] = Ur[j * HD + k0 + u];
        uh[u] = Uh[j * HD + k0 + u];
    }

    __shared__ float p_s[HD], r_s[HD], lmax_s[HD];
    if (tid < HD) lmax_s[tid] = -3.402823466e38f;
    int np1 = np_ptr[0] - 1;
    __syncthreads();

    for (int i = blockIdx.x; i < n_steps; i += gridDim.x) {
        int d = g_dep[i];
        if (d >= 0) {
            if (tid == 0) {
                int cnt = 0;
                while (g_ready[d] == 0) {
                    if (((++cnt) & 63) == 0) __nanosleep(64);
                }
                __threadfence();  // acquire side
            }
            __syncthreads();
            if (tid < HD) p_s[tid] = __ldcg(&g_h[(size_t)d * HD + tid]);
        } else {
            if (tid < HD) p_s[tid] = 0.f;
        }
        __syncthreads();

        float sz = 0.f, sr = 0.f, pk[16];
#pragma unroll
        for (int u = 0; u < 16; u++) {
            float p = p_s[k0 + u];
            pk[u] = p;
            sz = fmaf(uz[u], p, sz);
            sr = fmaf(ur[u], p, sr);
        }
        sz += __shfl_xor_sync(0xffffffffu, sz, 1);
        sz += __shfl_xor_sync(0xffffffffu, sz, 2);
        sr += __shfl_xor_sync(0xffffffffu, sr, 1);
        sr += __shfl_xor_sync(0xffffffffu, sr, 2);

        float zz = fminf(fmaxf(0.2f * (sz + g_az[(size_t)i * HD + j]) + 0.5f, 0.f), 1.f);
        float rr = fminf(fmaxf(0.2f * (sr + g_ar[(size_t)i * HD + j]) + 0.5f, 0.f), 1.f);
        if (leader) r_s[j] = rr;
        __syncthreads();

        float sh = 0.f;
#pragma unroll
        for (int u = 0; u < 16; u++) sh = fmaf(uh[u], pk[u] * r_s[k0 + u], sh);
        sh += __shfl_xor_sync(0xffffffffu, sh, 1);
        sh += __shfl_xor_sync(0xffffffffu, sh, 2);

        float c = tanhf(sh + g_ah[(size_t)i * HD + j]);
        float hv = zz * p_s[j] + (1.f - zz) * c;

        if (leader) {
            g_h[(size_t)i * HD + j] = hv;
            if (i >= np1) lmax_s[j] = fmaxf(lmax_s[j], hv);
        }
        __syncthreads();  // all h stores issued; all p_s/r_s reads done
        if (tid == 0) {
            __threadfence();      // release h stores to GPU scope
            g_ready[i] = 1;       // volatile store
        }
    }

    __syncthreads();
    if (tid < HD) {
        float f = lmax_s[tid];
        unsigned u = __float_as_uint(f);
        u = (u & 0x80000000u) ? ~u : (u | 0x80000000u);
        atomicMax(&g_max[tid], u);
    }
}

// ---------------- decode ordered-uint max into output ----------------
__global__ void final_kernel(float* __restrict__ out) {
    int t = threadIdx.x;
    if (t >= HD) return;
    unsigned u = g_max[t];
    unsigned b = (u & 0x80000000u) ? (u & 0x7fffffffu) : ~u;
    out[t] = __uint_as_float(b);
}

// ---------------- launch ----------------
extern "C" void kernel_launch(void* const* d_in, const int* in_sizes, int n_in,
                              void* d_out, int out_size) {
    const float* xw = (const float*)d_in[0];
    const int* xi = (const int*)d_in[1];
    const int* tree = (const int*)d_in[2];
    const int* np = (const int*)d_in[3];
    const float* emb = (const float*)d_in[4];
    const float* Wz = (const float*)d_in[5];
    const float* Uz = (const float*)d_in[6];
    const float* bz = (const float*)d_in[7];
    const float* Wr = (const float*)d_in[8];
    const float* Ur = (const float*)d_in[9];
    const float* br = (const float*)d_in[10];
    const float* Wh = (const float*)d_in[11];
    const float* Uh = (const float*)d_in[12];
    const float* bh = (const float*)d_in[13];

    int N = in_sizes[2] / 2;      // tree is [N,2]
    int L = in_sizes[0] / N;      // x_word is [N,L]
    int n_steps = N - 1;

    int prep_elems = n_steps > (HD * HD) ? n_steps : (HD * HD);
    prep_kernel<<<(prep_elems + 255) / 256, 256>>>(Wz, Wr, Wh, tree, n_steps);
    dep_kernel<<<(n_steps + 255) / 256, 256>>>(tree, n_steps);
    gather_kernel<<<n_steps, HD>>>(xw, xi, emb, bz, br, bh, L);
    recur_kernel<<<296, 256>>>(Uz, Ur, Uh, np, n_steps);
    final_kernel<<<1, HD>>>((float*)d_out);
}

// round 2
// speedup vs baseline: 4.6030x; 4.6030x over previous
#include <cuda_runtime.h>
#include <cuda_fp16.h>

#define MAXN 8192
#define HD 64
#define SLOTS 32
#define EMB_MAX (50000 * HD)
#define RECUR_BLOCKS 296
#define WARPS_PER_BLK 8
#define TOTAL_WARPS (RECUR_BLOCKS * WARPS_PER_BLK)

// ---------------- static device scratch ----------------
__device__ float g_WzT[HD * HD];
__device__ float g_WrT[HD * HD];
__device__ float g_WhT[HD * HD];
__device__ float g_UzT[HD * HD];
__device__ float g_UrT[HD * HD];
__device__ float g_UhT[HD * HD];
__device__ __half g_embh[EMB_MAX];
__device__ float g_az[MAXN * HD];
__device__ float g_ar[MAXN * HD];
__device__ float g_ah[MAXN * HD];
__device__ float g_h[MAXN * HD];
__device__ int g_dep[MAXN];
__device__ int g_wr[MAXN];
__device__ int g_cnt[MAXN];
__device__ int g_buck[MAXN * SLOTS];
__device__ volatile int g_ready[MAXN];
__device__ unsigned g_max[HD];

// ---------------- prep: transposes, flags, counters ----------------
__global__ void prep_kernel(const float* __restrict__ Wz, const float* __restrict__ Wr,
                            const float* __restrict__ Wh, const float* __restrict__ Uz,
                            const float* __restrict__ Ur, const float* __restrict__ Uh,
                            const int* __restrict__ tree, int n_steps) {
    int t = blockIdx.x * blockDim.x + threadIdx.x;
    if (t < HD * HD) {
        int j = t / HD, k = t % HD;
        g_WzT[k * HD + j] = Wz[t];
        g_WrT[k * HD + j] = Wr[t];
        g_WhT[k * HD + j] = Wh[t];
        g_UzT[k * HD + j] = Uz[t];
        g_UrT[k * HD + j] = Ur[t];
        g_UhT[k * HD + j] = Uh[t];
    }
    if (t < n_steps) {
        g_wr[t] = tree[2 * t + 1];
        g_ready[t] = 0;
    }
    if (t < MAXN) g_cnt[t] = 0;
    if (t < HD) g_max[t] = 0u;
}

// ---------------- embedding fp32 -> fp16 ----------------
__global__ void conv_kernel(const float* __restrict__ emb, int total) {
    int e = (blockIdx.x * blockDim.x + threadIdx.x) * 4;
    if (e + 3 < total) {
        float4 f = *reinterpret_cast<const float4*>(emb + e);
        __half2 h0 = __floats2half2_rn(f.x, f.y);
        __half2 h1 = __floats2half2_rn(f.z, f.w);
        *reinterpret_cast<__half2*>(g_embh + e) = h0;
        *reinterpret_cast<__half2*>(g_embh + e + 2) = h1;
    }
}

// ---------------- bucket fill: writes per node ----------------
__global__ void fill_kernel(const int* __restrict__ tree, int n_steps) {
    int i = blockIdx.x * blockDim.x + threadIdx.x;
    if (i >= n_steps) return;
    int v = tree[2 * i + 1];
    int s = atomicAdd(&g_cnt[v], 1);
    if (s < SLOTS) g_buck[v * SLOTS + s] = i;
}

// ---------------- dep query: last write to node tree[i,0] before i ----------------
__global__ void depq_kernel(const int* __restrict__ tree, int n_steps) {
    int i = blockIdx.x * blockDim.x + threadIdx.x;
    if (i >= n_steps) return;
    int v = tree[2 * i];
    int c = g_cnt[v];
    int d = -1;
    if (c <= SLOTS) {
        for (int s = 0; s < c; s++) {
            int j = g_buck[v * SLOTS + s];
            if (j < i && j > d) d = j;
        }
    } else {
        for (int j = i - 1; j >= 0; --j) {
            if (g_wr[j] == v) { d = j; break; }
        }
    }
    g_dep[i] = d;
}

// ---------------- gather: xe = emb^T @ w (fp16 emb), then a_* = W_* xe + b_* ----------------
__global__ void __launch_bounds__(128)
gather_kernel(const float* __restrict__ xw, const int* __restrict__ xi,
              const float* __restrict__ bz, const float* __restrict__ br,
              const float* __restrict__ bh, int L) {
    int i = blockIdx.x;
    int t = threadIdx.x;
    __shared__ float ws[512];
    __shared__ int is_[512];
    __shared__ float part[16][HD];
    __shared__ float xe_s[HD];

    const float* xwrow = xw + (size_t)i * L;
    const int* xirow = xi + (size_t)i * L;

    int rl = t & 7;        // 16B chunk within row: dims rl*8 .. rl*8+7
    int rg = t >> 3;       // row group 0..15
    float2 acc0 = {0.f, 0.f}, acc1 = {0.f, 0.f}, acc2 = {0.f, 0.f}, acc3 = {0.f, 0.f};

    for (int base = 0; base < L; base += 512) {
        int chunk = min(512, L - base);
        __syncthreads();
        for (int l = t; l < chunk; l += 128) {
            ws[l] = xwrow[base + l];
            is_[l] = xirow[base + l];
        }
        __syncthreads();
#pragma unroll 4
        for (int l = rg; l < chunk; l += 16) {
            float w = ws[l];
            const uint4* p = reinterpret_cast<const uint4*>(
                g_embh + (size_t)is_[l] * HD + rl * 8);
            uint4 u = __ldg(p);
            __half2 h0 = *reinterpret_cast<__half2*>(&u.x);
            __half2 h1 = *reinterpret_cast<__half2*>(&u.y);
            __half2 h2 = *reinterpret_cast<__half2*>(&u.z);
            __half2 h3 = *reinterpret_cast<__half2*>(&u.w);
            float2 f0 = __half22float2(h0);
            float2 f1 = __half22float2(h1);
            float2 f2 = __half22float2(h2);
            float2 f3 = __half22float2(h3);
            acc0.x = fmaf(w, f0.x, acc0.x); acc0.y = fmaf(w, f0.y, acc0.y);
            acc1.x = fmaf(w, f1.x, acc1.x); acc1.y = fmaf(w, f1.y, acc1.y);
            acc2.x = fmaf(w, f2.x, acc2.x); acc2.y = fmaf(w, f2.y, acc2.y);
            acc3.x = fmaf(w, f3.x, acc3.x); acc3.y = fmaf(w, f3.y, acc3.y);
        }
    }
    __syncthreads();
    int d0 = rl * 8;
    part[rg][d0 + 0] = acc0.x; part[rg][d0 + 1] = acc0.y;
    part[rg][d0 + 2] = acc1.x; part[rg][d0 + 3] = acc1.y;
    part[rg][d0 + 4] = acc2.x; part[rg][d0 + 5] = acc2.y;
    part[rg][d0 + 6] = acc3.x; part[rg][d0 + 7] = acc3.y;
    __syncthreads();
    if (t < HD) {
        float xe = 0.f;
#pragma unroll
        for (int g = 0; g < 16; g++) xe += part[g][t];
        xe_s[t] = xe;
    }
    __syncthreads();
    if (t < HD) {
        float az = bz[t], ar = br[t], ah = bh[t];
#pragma unroll 8
        for (int k = 0; k < HD; k++) {
            float x = xe_s[k];
            az = fmaf(g_WzT[k * HD + t], x, az);
            ar = fmaf(g_WrT[k * HD + t], x, ar);
            ah = fmaf(g_WhT[k * HD + t], x, ah);
        }
        g_az[(size_t)i * HD + t] = az;
        g_ar[(size_t)i * HD + t] = ar;
        g_ah[(size_t)i * HD + t] = ah;
    }
}

// ---------------- dataflow recurrence: one step per WARP ----------------
__global__ void __launch_bounds__(256, 2)
recur_kernel(const int* __restrict__ np_ptr, int n_steps) {
    __shared__ float su[3][HD * HD];   // 48KB: UzT, UrT, UhT  ([k][j], j fast)
    int tid = threadIdx.x;
    int wid = tid >> 5, l = tid & 31;

    for (int idx = tid; idx < HD * HD; idx += 256) {
        su[0][idx] = g_UzT[idx];
        su[1][idx] = g_UrT[idx];
        su[2][idx] = g_UhT[idx];
    }
    int np1 = np_ptr[0] - 1;
    __syncthreads();

    int gw = blockIdx.x * WARPS_PER_BLK + wid;   // global warp id
    float2 lm = {-3.402823466e38f, -3.402823466e38f};

    for (int i = gw; i < n_steps; i += TOTAL_WARPS) {
        // prefetch a-vectors (independent of dependency)
        float2 az2 = __ldg(reinterpret_cast<const float2*>(g_az + (size_t)i * HD) + l);
        float2 ar2 = __ldg(reinterpret_cast<const float2*>(g_ar + (size_t)i * HD) + l);
        float2 ah2 = __ldg(reinterpret_cast<const float2*>(g_ah + (size_t)i * HD) + l);

        int d = (l == 0) ? g_dep[i] : 0;
        d = __shfl_sync(0xffffffffu, d, 0);

        float2 p2;
        if (d >= 0) {
            if (l == 0) {
                int cnt = 0;
                while (g_ready[d] == 0) {
                    if (((++cnt) & 31) == 0) __nanosleep(64);
                }
            }
            __syncwarp();
            p2 = __ldcg(reinterpret_cast<const float2*>(g_h + (size_t)d * HD) + l);
        } else {
            p2 = make_float2(0.f, 0.f);
        }

        // gate z, r:  acc over k of U[j][k] * p[k]
        float2 accz = {0.f, 0.f}, accr = {0.f, 0.f};
#pragma unroll
        for (int k2 = 0; k2 < 32; k2++) {
            float2 pk2;
            pk2.x = __shfl_sync(0xffffffffu, p2.x, k2);
            pk2.y = __shfl_sync(0xffffffffu, p2.y, k2);
            float2 uz_a = *reinterpret_cast<float2*>(&su[0][(2 * k2) * HD + 2 * l]);
            float2 uz_b = *reinterpret_cast<float2*>(&su[0][(2 * k2 + 1) * HD + 2 * l]);
            float2 ur_a = *reinterpret_cast<float2*>(&su[1][(2 * k2) * HD + 2 * l]);
            float2 ur_b = *reinterpret_cast<float2*>(&su[1][(2 * k2 + 1) * HD + 2 * l]);
            accz.x = fmaf(uz_a.x, pk2.x, accz.x); accz.y = fmaf(uz_a.y, pk2.x, accz.y);
            accz.x = fmaf(uz_b.x, pk2.y, accz.x); accz.y = fmaf(uz_b.y, pk2.y, accz.y);
            accr.x = fmaf(ur_a.x, pk2.x, accr.x); accr.y = fmaf(ur_a.y, pk2.x, accr.y);
            accr.x = fmaf(ur_b.x, pk2.y, accr.x); accr.y = fmaf(ur_b.y, pk2.y, accr.y);
        }
        float2 z2, r2;
        z2.x = fminf(fmaxf(0.2f * (accz.x + az2.x) + 0.5f, 0.f), 1.f);
        z2.y = fminf(fmaxf(0.2f * (accz.y + az2.y) + 0.5f, 0.f), 1.f);
        r2.x = fminf(fmaxf(0.2f * (accr.x + ar2.x) + 0.5f, 0.f), 1.f);
        r2.y = fminf(fmaxf(0.2f * (accr.y + ar2.y) + 0.5f, 0.f), 1.f);

        float2 pr2 = make_float2(p2.x * r2.x, p2.y * r2.y);

        // gate h: acc over k of Uh[j][k] * (p[k]*r[k])
        float2 acch = {0.f, 0.f};
#pragma unroll
        for (int k2 = 0; k2 < 32; k2++) {
            float2 prk2;
            prk2.x = __shfl_sync(0xffffffffu, pr2.x, k2);
            prk2.y = __shfl_sync(0xffffffffu, pr2.y, k2);
            float2 uh_a = *reinterpret_cast<float2*>(&su[2][(2 * k2) * HD + 2 * l]);
            float2 uh_b = *reinterpret_cast<float2*>(&su[2][(2 * k2 + 1) * HD + 2 * l]);
            acch.x = fmaf(uh_a.x, prk2.x, acch.x); acch.y = fmaf(uh_a.y, prk2.x, acch.y);
            acch.x = fmaf(uh_b.x, prk2.y, acch.x); acch.y = fmaf(uh_b.y, prk2.y, acch.y);
        }
        float2 c2, h2;
        c2.x = tanhf(acch.x + ah2.x);
        c2.y = tanhf(acch.y + ah2.y);
        h2.x = z2.x * p2.x + (1.f - z2.x) * c2.x;
        h2.y = z2.y * p2.y + (1.f - z2.y) * c2.y;

        __stcg(reinterpret_cast<float2*>(g_h + (size_t)i * HD) + l, h2);
        if (i >= np1) {
            lm.x = fmaxf(lm.x, h2.x);
            lm.y = fmaxf(lm.y, h2.y);
        }
        __threadfence();          // release this lane's h store
        __syncwarp();             // all lanes' fences done
        if (l == 0) g_ready[i] = 1;
    }

    // fold local max into global ordered-uint max
    unsigned ux = __float_as_uint(lm.x);
    ux = (ux & 0x80000000u) ? ~ux : (ux | 0x80000000u);
    unsigned uy = __float_as_uint(lm.y);
    uy = (uy & 0x80000000u) ? ~uy : (uy | 0x80000000u);
    atomicMax(&g_max[2 * l], ux);
    atomicMax(&g_max[2 * l + 1], uy);
}

// ---------------- decode ordered-uint max ----------------
__global__ void final_kernel(float* __restrict__ out) {
    int t = threadIdx.x;
    if (t >= HD) return;
    unsigned u = g_max[t];
    unsigned b = (u & 0x80000000u) ? (u & 0x7fffffffu) : ~u;
    out[t] = __uint_as_float(b);
}

// ---------------- launch ----------------
extern "C" void kernel_launch(void* const* d_in, const int* in_sizes, int n_in,
                              void* d_out, int out_size) {
    const float* xw = (const float*)d_in[0];
    const int* xi = (const int*)d_in[1];
    const int* tree = (const int*)d_in[2];
    const int* np = (const int*)d_in[3];
    const float* emb = (const float*)d_in[4];
    const float* Wz = (const float*)d_in[5];
    const float* Uz = (const float*)d_in[6];
    const float* bz = (const float*)d_in[7];
    const float* Wr = (const float*)d_in[8];
    const float* Ur = (const float*)d_in[9];
    const float* br = (const float*)d_in[10];
    const float* Wh = (const float*)d_in[11];
    const float* Uh = (const float*)d_in[12];
    const float* bh = (const float*)d_in[13];

    int N = in_sizes[2] / 2;      // tree is [N,2]
    int L = in_sizes[0] / N;      // x_word is [N,L]
    int n_steps = N - 1;
    int emb_total = in_sizes[4];  // V*H floats

    prep_kernel<<<(MAXN + 255) / 256, 256>>>(Wz, Wr, Wh, Uz, Ur, Uh, tree, n_steps);
    conv_kernel<<<(emb_total / 4 + 255) / 256, 256>>>(emb, emb_total);
    fill_kernel<<<(n_steps + 255) / 256, 256>>>(tree, n_steps);
    depq_kernel<<<(n_steps + 255) / 256, 256>>>(tree, n_steps);
    gather_kernel<<<n_steps, 128>>>(xw, xi, bz, br, bh, L);
    recur_kernel<<<RECUR_BLOCKS, 256>>>(np, n_steps);
    final_kernel<<<1, HD>>>((float*)d_out);
}

// round 3
// speedup vs baseline: 7.9557x; 1.7284x over previous
#include <cuda_runtime.h>
#include <cuda_fp16.h>
#include <cstdint>

#define MAXN 8192
#define HD 64
#define SLOTS 32
#define EMB_MAX (50000 * HD)
#define BLKS 296
#define WPB 8
#define TW (BLKS * WPB)

// ---------------- static device scratch ----------------
__device__ __half g_embh[EMB_MAX];
__device__ float g_h[MAXN * HD];
__device__ int g_wr[MAXN];
__device__ int g_cnt[MAXN];
__device__ int g_buck[MAXN * SLOTS];
__device__ volatile int g_ready[MAXN];
__device__ unsigned g_max[HD];

// ---------------- prep: fp16 embedding conversion + flag/counter reset ----------------
__global__ void prep_kernel(const float* __restrict__ emb, const int* __restrict__ tree,
                            int n_steps, int emb_total) {
    int t = blockIdx.x * blockDim.x + threadIdx.x;
    int e = t * 4;
    if (e + 3 < emb_total) {
        float4 f = *reinterpret_cast<const float4*>(emb + e);
        __half2 h0 = __floats2half2_rn(f.x, f.y);
        __half2 h1 = __floats2half2_rn(f.z, f.w);
        *reinterpret_cast<__half2*>(g_embh + e) = h0;
        *reinterpret_cast<__half2*>(g_embh + e + 2) = h1;
    }
    if (t < n_steps) {
        g_wr[t] = tree[2 * t + 1];
        g_ready[t] = 0;
    }
    if (t < MAXN) g_cnt[t] = 0;
    if (t < HD) g_max[t] = 0u;
}

// ---------------- bucket fill: writes per node ----------------
__global__ void fill_kernel(const int* __restrict__ tree, int n_steps) {
    int i = blockIdx.x * blockDim.x + threadIdx.x;
    if (i >= n_steps) return;
    int v = tree[2 * i + 1];
    int s = atomicAdd(&g_cnt[v], 1);
    if (s < SLOTS) g_buck[v * SLOTS + s] = i;
}

// ---------------- fused gather + GRU dataflow kernel (one step per warp) ----------------
__global__ void __launch_bounds__(256, 2)
fused_kernel(const float* __restrict__ xw, const int* __restrict__ xi,
             const int* __restrict__ tree,
             const float* __restrict__ Wz, const float* __restrict__ Uz,
             const float* __restrict__ bz,
             const float* __restrict__ Wr, const float* __restrict__ Ur,
             const float* __restrict__ br,
             const float* __restrict__ Wh, const float* __restrict__ Uh,
             const float* __restrict__ bh,
             const int* __restrict__ np_ptr, int L, int n_steps) {
    extern __shared__ float sm[];
    float* sWz = sm;              // [k*64 + j], transposed
    float* sWr = sm + 4096;
    float* sWh = sm + 8192;
    float* sUz = sm + 12288;
    float* sUr = sm + 16384;
    float* sUh = sm + 20480;
    float* sXe = sm + 24576;      // per-warp [wid*64]
    float* sP  = sm + 24576 + 512;
    float* sPr = sm + 24576 + 1024;

    int tid = threadIdx.x;
    int wid = tid >> 5, l = tid & 31;
    int rl = l & 7, rg = l >> 3;

    // load + transpose all six 64x64 matrices into smem
    for (int t = tid; t < 4096; t += 256) {
        int j = t >> 6, k = t & 63;
        sWz[k * 64 + j] = Wz[t];
        sWr[k * 64 + j] = Wr[t];
        sWh[k * 64 + j] = Wh[t];
        sUz[k * 64 + j] = Uz[t];
        sUr[k * 64 + j] = Ur[t];
        sUh[k * 64 + j] = Uh[t];
    }
    float2 bz2 = reinterpret_cast<const float2*>(bz)[l];
    float2 br2 = reinterpret_cast<const float2*>(br)[l];
    float2 bh2 = reinterpret_cast<const float2*>(bh)[l];
    int np1 = np_ptr[0] - 1;
    __syncthreads();

    float* xe_w = sXe + wid * 64;
    float* p_w  = sP + wid * 64;
    float* pr_w = sPr + wid * 64;
    float2 lm = make_float2(-3.402823466e38f, -3.402823466e38f);

    for (int i = blockIdx.x * WPB + wid; i < n_steps; i += TW) {
        // ---- dep(i): last j<i writing node tree[i,0] (warp-cooperative bucket scan) ----
        int v = tree[2 * i];
        int c = g_cnt[v];
        int d = -1;
        if (c <= SLOTS) {
            if (l < c) {
                int j = g_buck[v * SLOTS + l];
                if (j < i) d = j;
            }
        } else {
            if (l == 0) {
                for (int j = i - 1; j >= 0; --j)
                    if (g_wr[j] == v) { d = j; break; }
            }
        }
        d = __reduce_max_sync(0xffffffffu, d);

        // ---- gather: xe = sum_l w[l] * emb_h[idx[l]]  (this lane: dims rl*8..rl*8+7) ----
        float acc[8];
#pragma unroll
        for (int u = 0; u < 8; u++) acc[u] = 0.f;
        const float* xwr = xw + (size_t)i * L;
        const int* xir = xi + (size_t)i * L;
#pragma unroll 4
        for (int r0 = rg; r0 < L; r0 += 4) {
            float w = __ldg(&xwr[r0]);
            int ix = __ldg(&xir[r0]);
            uint4 u4 = __ldg(reinterpret_cast<const uint4*>(
                g_embh + (size_t)ix * HD + rl * 8));
            float2 f0 = __half22float2(*reinterpret_cast<__half2*>(&u4.x));
            float2 f1 = __half22float2(*reinterpret_cast<__half2*>(&u4.y));
            float2 f2 = __half22float2(*reinterpret_cast<__half2*>(&u4.z));
            float2 f3 = __half22float2(*reinterpret_cast<__half2*>(&u4.w));
            acc[0] = fmaf(w, f0.x, acc[0]); acc[1] = fmaf(w, f0.y, acc[1]);
            acc[2] = fmaf(w, f1.x, acc[2]); acc[3] = fmaf(w, f1.y, acc[3]);
            acc[4] = fmaf(w, f2.x, acc[4]); acc[5] = fmaf(w, f2.y, acc[5]);
            acc[6] = fmaf(w, f3.x, acc[6]); acc[7] = fmaf(w, f3.y, acc[7]);
        }
#pragma unroll
        for (int u = 0; u < 8; u++) {
            acc[u] += __shfl_xor_sync(0xffffffffu, acc[u], 8);
            acc[u] += __shfl_xor_sync(0xffffffffu, acc[u], 16);
        }
        if (rg == 0) {
#pragma unroll
            for (int u = 0; u < 8; u++) xe_w[rl * 8 + u] = acc[u];
        }
        __syncwarp();

        // ---- W matvecs (before dep wait): a_* = W_* xe + b_*  (lane j-pair = 2l,2l+1) ----
        float2 azA = bz2, arA = br2, ahA = bh2;
        float2 azB = {0.f, 0.f}, arB = {0.f, 0.f}, ahB = {0.f, 0.f};
#pragma unroll
        for (int k = 0; k < 64; k += 2) {
            float x0 = xe_w[k], x1 = xe_w[k + 1];
            float2 m0, m1;
            m0 = *reinterpret_cast<float2*>(&sWz[k * 64 + 2 * l]);
            m1 = *reinterpret_cast<float2*>(&sWz[(k + 1) * 64 + 2 * l]);
            azA.x = fmaf(m0.x, x0, azA.x); azA.y = fmaf(m0.y, x0, azA.y);
            azB.x = fmaf(m1.x, x1, azB.x); azB.y = fmaf(m1.y, x1, azB.y);
            m0 = *reinterpret_cast<float2*>(&sWr[k * 64 + 2 * l]);
            m1 = *reinterpret_cast<float2*>(&sWr[(k + 1) * 64 + 2 * l]);
            arA.x = fmaf(m0.x, x0, arA.x); arA.y = fmaf(m0.y, x0, arA.y);
            arB.x = fmaf(m1.x, x1, arB.x); arB.y = fmaf(m1.y, x1, arB.y);
            m0 = *reinterpret_cast<float2*>(&sWh[k * 64 + 2 * l]);
            m1 = *reinterpret_cast<float2*>(&sWh[(k + 1) * 64 + 2 * l]);
            ahA.x = fmaf(m0.x, x0, ahA.x); ahA.y = fmaf(m0.y, x0, ahA.y);
            ahB.x = fmaf(m1.x, x1, ahB.x); ahB.y = fmaf(m1.y, x1, ahB.y);
        }
        float2 az2 = make_float2(azA.x + azB.x, azA.y + azB.y);
        float2 ar2 = make_float2(arA.x + arB.x, arA.y + arB.y);
        float2 ah2 = make_float2(ahA.x + ahB.x, ahA.y + ahB.y);

        // ---- wait for parent h ----
        float2 p2;
        if (d >= 0) {
            if (l == 0) {
                int cnt = 0;
                while (g_ready[d] == 0) {
                    if (((++cnt) & 31) == 0) __nanosleep(64);
                }
            }
            __syncwarp();
            p2 = __ldcg(reinterpret_cast<const float2*>(g_h + (size_t)d * HD) + l);
        } else {
            p2 = make_float2(0.f, 0.f);
        }
        *reinterpret_cast<float2*>(&p_w[2 * l]) = p2;
        __syncwarp();

        // ---- U z/r matvecs ----
        float2 szA = {0.f, 0.f}, srA = {0.f, 0.f}, szB = {0.f, 0.f}, srB = {0.f, 0.f};
#pragma unroll
        for (int k = 0; k < 64; k += 2) {
            float x0 = p_w[k], x1 = p_w[k + 1];
            float2 m0, m1;
            m0 = *reinterpret_cast<float2*>(&sUz[k * 64 + 2 * l]);
            m1 = *reinterpret_cast<float2*>(&sUz[(k + 1) * 64 + 2 * l]);
            szA.x = fmaf(m0.x, x0, szA.x); szA.y = fmaf(m0.y, x0, szA.y);
            szB.x = fmaf(m1.x, x1, szB.x); szB.y = fmaf(m1.y, x1, szB.y);
            m0 = *reinterpret_cast<float2*>(&sUr[k * 64 + 2 * l]);
            m1 = *reinterpret_cast<float2*>(&sUr[(k + 1) * 64 + 2 * l]);
            srA.x = fmaf(m0.x, x0, srA.x); srA.y = fmaf(m0.y, x0, srA.y);
            srB.x = fmaf(m1.x, x1, srB.x); srB.y = fmaf(m1.y, x1, srB.y);
        }
        float2 z2, r2;
        z2.x = fminf(fmaxf(0.2f * (szA.x + szB.x + az2.x) + 0.5f, 0.f), 1.f);
        z2.y = fminf(fmaxf(0.2f * (szA.y + szB.y + az2.y) + 0.5f, 0.f), 1.f);
        r2.x = fminf(fmaxf(0.2f * (srA.x + srB.x + ar2.x) + 0.5f, 0.f), 1.f);
        r2.y = fminf(fmaxf(0.2f * (srA.y + srB.y + ar2.y) + 0.5f, 0.f), 1.f);
        float2 pr2 = make_float2(p2.x * r2.x, p2.y * r2.y);
        *reinterpret_cast<float2*>(&pr_w[2 * l]) = pr2;
        __syncwarp();

        // ---- Uh matvec ----
        float2 shA = {0.f, 0.f}, shB = {0.f, 0.f};
#pragma unroll
        for (int k = 0; k < 64; k += 2) {
            float x0 = pr_w[k], x1 = pr_w[k + 1];
            float2 m0 = *reinterpret_cast<float2*>(&sUh[k * 64 + 2 * l]);
            float2 m1 = *reinterpret_cast<float2*>(&sUh[(k + 1) * 64 + 2 * l]);
            shA.x = fmaf(m0.x, x0, shA.x); shA.y = fmaf(m0.y, x0, shA.y);
            shB.x = fmaf(m1.x, x1, shB.x); shB.y = fmaf(m1.y, x1, shB.y);
        }
        float2 c2, h2;
        c2.x = tanhf(shA.x + shB.x + ah2.x);
        c2.y = tanhf(shA.y + shB.y + ah2.y);
        h2.x = z2.x * p2.x + (1.f - z2.x) * c2.x;
        h2.y = z2.y * p2.y + (1.f - z2.y) * c2.y;

        __stcg(reinterpret_cast<float2*>(g_h + (size_t)i * HD) + l, h2);
        if (i >= np1) {
            lm.x = fmaxf(lm.x, h2.x);
            lm.y = fmaxf(lm.y, h2.y);
        }
        __threadfence();          // release h stores
        __syncwarp();             // all lanes fenced
        if (l == 0) g_ready[i] = 1;
    }

    unsigned ux = __float_as_uint(lm.x);
    ux = (ux & 0x80000000u) ? ~ux : (ux | 0x80000000u);
    unsigned uy = __float_as_uint(lm.y);
    uy = (uy & 0x80000000u) ? ~uy : (uy | 0x80000000u);
    atomicMax(&g_max[2 * l], ux);
    atomicMax(&g_max[2 * l + 1], uy);
}

// ---------------- decode ordered-uint max ----------------
__global__ void final_kernel(float* __restrict__ out) {
    int t = threadIdx.x;
    if (t >= HD) return;
    unsigned u = g_max[t];
    unsigned b = (u & 0x80000000u) ? (u & 0x7fffffffu) : ~u;
    out[t] = __uint_as_float(b);
}

// ---------------- launch ----------------
extern "C" void kernel_launch(void* const* d_in, const int* in_sizes, int n_in,
                              void* d_out, int out_size) {
    const float* xw = (const float*)d_in[0];
    const int* xi = (const int*)d_in[1];
    const int* tree = (const int*)d_in[2];
    const int* np = (const int*)d_in[3];
    const float* emb = (const float*)d_in[4];
    const float* Wz = (const float*)d_in[5];
    const float* Uz = (const float*)d_in[6];
    const float* bz = (const float*)d_in[7];
    const float* Wr = (const float*)d_in[8];
    const float* Ur = (const float*)d_in[9];
    const float* br = (const float*)d_in[10];
    const float* Wh = (const float*)d_in[11];
    const float* Uh = (const float*)d_in[12];
    const float* bh = (const float*)d_in[13];

    int N = in_sizes[2] / 2;      // tree is [N,2]
    int L = in_sizes[0] / N;      // x_word is [N,L]
    int n_steps = N - 1;
    int emb_total = in_sizes[4];  // V*H floats

    static int smem_set = 0;
    const int SMEM_BYTES = (24576 + 1536) * 4;  // 104448
    if (!smem_set) {
        cudaFuncSetAttribute(fused_kernel,
                             cudaFuncAttributeMaxDynamicSharedMemorySize, SMEM_BYTES);
        smem_set = 1;
    }

    int prep_threads = (emb_total + 3) / 4;
    if (prep_threads < MAXN) prep_threads = MAXN;
    prep_kernel<<<(prep_threads + 255) / 256, 256>>>(emb, tree, n_steps, emb_total);
    fill_kernel<<<(n_steps + 255) / 256, 256>>>(tree, n_steps);
    fused_kernel<<<BLKS, 256, SMEM_BYTES>>>(xw, xi, tree, Wz, Uz, bz, Wr, Ur, br,
                                            Wh, Uh, bh, np, L, n_steps);
    final_kernel<<<1, HD>>>((float*)d_out);
}

// round 4
// speedup vs baseline: 8.6667x; 1.0894x over previous
#include <cuda_runtime.h>
#include <cuda_fp16.h>
#include <cstdint>

#define MAXN 8192
#define HD 64
#define SLOTS 32
#define EMB_MAX (50000 * HD)
#define BLKS 296
#define WPB 8
#define TW (BLKS * WPB)
#define GCH 128   // gather chunk rows

// ---------------- static device scratch ----------------
__device__ __half g_embh[EMB_MAX];
__device__ float g_h[MAXN * HD];
__device__ int g_wr[MAXN];
__device__ int g_cnt[MAXN];
__device__ int g_buck[MAXN * SLOTS];
__device__ volatile int g_ready[MAXN];
__device__ unsigned g_max[HD];
__device__ unsigned g_done;

// ---------------- prep: fp16 embedding conversion + state reset ----------------
__global__ void prep_kernel(const float* __restrict__ emb, const int* __restrict__ tree,
                            int n_steps, int emb_total) {
    int t = blockIdx.x * blockDim.x + threadIdx.x;
    int e = t * 4;
    if (e + 3 < emb_total) {
        float4 f = *reinterpret_cast<const float4*>(emb + e);
        *reinterpret_cast<__half2*>(g_embh + e) = __floats2half2_rn(f.x, f.y);
        *reinterpret_cast<__half2*>(g_embh + e + 2) = __floats2half2_rn(f.z, f.w);
    }
    if (t < n_steps) {
        g_wr[t] = tree[2 * t + 1];
        g_ready[t] = 0;
    }
    if (t < MAXN) g_cnt[t] = 0;
    if (t < HD) g_max[t] = 0u;
    if (t == 0) g_done = 0u;
}

// ---------------- bucket fill: writes per node ----------------
__global__ void fill_kernel(const int* __restrict__ tree, int n_steps) {
    int i = blockIdx.x * blockDim.x + threadIdx.x;
    if (i >= n_steps) return;
    int v = tree[2 * i + 1];
    int s = atomicAdd(&g_cnt[v], 1);
    if (s < SLOTS) g_buck[v * SLOTS + s] = i;
}

// ---------------- gather one 128-row chunk into acc regs ----------------
__device__ __forceinline__ void gather_chunk(const float* __restrict__ xwr,
                                             const int* __restrict__ xir,
                                             int r0, int rl, int rg, float acc[8]) {
#pragma unroll 2
    for (int rr = 0; rr < GCH; rr += 16) {
        int rbase = r0 + rr + 4 * rg;
        float4 w4 = __ldg(reinterpret_cast<const float4*>(xwr + rbase));
        int4 i4 = __ldg(reinterpret_cast<const int4*>(xir + rbase));
        uint4 u0 = __ldg(reinterpret_cast<const uint4*>(g_embh + (size_t)i4.x * HD + rl * 8));
        uint4 u1 = __ldg(reinterpret_cast<const uint4*>(g_embh + (size_t)i4.y * HD + rl * 8));
        uint4 u2 = __ldg(reinterpret_cast<const uint4*>(g_embh + (size_t)i4.z * HD + rl * 8));
        uint4 u3 = __ldg(reinterpret_cast<const uint4*>(g_embh + (size_t)i4.w * HD + rl * 8));
#define ACCUM(U, W)                                                              \
        {                                                                        \
            float2 f0 = __half22float2(*reinterpret_cast<__half2*>(&U.x));      \
            float2 f1 = __half22float2(*reinterpret_cast<__half2*>(&U.y));      \
            float2 f2 = __half22float2(*reinterpret_cast<__half2*>(&U.z));      \
            float2 f3 = __half22float2(*reinterpret_cast<__half2*>(&U.w));      \
            acc[0] = fmaf(W, f0.x, acc[0]); acc[1] = fmaf(W, f0.y, acc[1]);     \
            acc[2] = fmaf(W, f1.x, acc[2]); acc[3] = fmaf(W, f1.y, acc[3]);     \
            acc[4] = fmaf(W, f2.x, acc[4]); acc[5] = fmaf(W, f2.y, acc[5]);     \
            acc[6] = fmaf(W, f3.x, acc[6]); acc[7] = fmaf(W, f3.y, acc[7]);     \
        }
        ACCUM(u0, w4.x) ACCUM(u1, w4.y) ACCUM(u2, w4.z) ACCUM(u3, w4.w)
#undef ACCUM
    }
}

// ---------------- fused gather + GRU dataflow (one step per warp, pipelined) ----------------
__global__ void __launch_bounds__(256, 2)
fused_kernel(const float* __restrict__ xw, const int* __restrict__ xi,
             const int* __restrict__ tree,
             const float* __restrict__ Wz, const float* __restrict__ Uz,
             const float* __restrict__ bz,
             const float* __restrict__ Wr, const float* __restrict__ Ur,
             const float* __restrict__ br,
             const float* __restrict__ Wh, const float* __restrict__ Uh,
             const float* __restrict__ bh,
             const int* __restrict__ np_ptr, int L, int n_steps,
             float* __restrict__ out) {
    extern __shared__ float sm[];
    float* sWzr = sm;             // [k*128 + 4l + {Wz2l,Wz2l+1,Wr2l,Wr2l+1}]
    float* sWh2 = sm + 8192;      // [kp*128 + 4l + {Wh[2l][2kp],Wh[2l+1][2kp],Wh[2l][2kp+1],Wh[2l+1][2kp+1]}]
    float* sUzr = sm + 12288;
    float* sUh2 = sm + 20480;
    float* sXe = sm + 24576;      // per-warp 64
    float* sP  = sm + 25088;
    float* sPr = sm + 25600;

    int tid = threadIdx.x;
    int wid = tid >> 5, l = tid & 31;
    int rl = l & 7, rg = l >> 3;

    // pack weight matrices into interleaved smem layouts
    for (int t = tid; t < 8192; t += 256) {
        int k = t >> 7, q = t & 127, lane = q >> 2, c = q & 3;
        int j = 2 * lane + (c & 1);
        sWzr[t] = (c < 2 ? Wz : Wr)[j * 64 + k];
        sUzr[t] = (c < 2 ? Uz : Ur)[j * 64 + k];
    }
    for (int t = tid; t < 4096; t += 256) {
        int kp = t >> 7, q = t & 127, lane = q >> 2, c = q & 3;
        int j = 2 * lane + (c & 1);
        int k = 2 * kp + (c >> 1);
        sWh2[t] = Wh[j * 64 + k];
        sUh2[t] = Uh[j * 64 + k];
    }
    float2 bz2 = reinterpret_cast<const float2*>(bz)[l];
    float2 br2 = reinterpret_cast<const float2*>(br)[l];
    float2 bh2 = reinterpret_cast<const float2*>(bh)[l];
    int np1 = np_ptr[0] - 1;
    __syncthreads();

    const float4* Wzr4 = reinterpret_cast<const float4*>(sWzr);
    const float4* Wh4  = reinterpret_cast<const float4*>(sWh2);
    const float4* Uzr4 = reinterpret_cast<const float4*>(sUzr);
    const float4* Uh4  = reinterpret_cast<const float4*>(sUh2);
    float* xe_w = sXe + wid * 64;
    float* p_w  = sP + wid * 64;
    float* pr_w = sPr + wid * 64;
    float2 lm = make_float2(-3.402823466e38f, -3.402823466e38f);

    // preamble: gather first owned step
    int i0 = blockIdx.x * WPB + wid;
    float acc[8] = {0.f, 0.f, 0.f, 0.f, 0.f, 0.f, 0.f, 0.f};
    if (i0 < n_steps) {
        const float* xwr = xw + (size_t)i0 * L;
        const int* xir = xi + (size_t)i0 * L;
        for (int r0 = 0; r0 < L; r0 += GCH) gather_chunk(xwr, xir, r0, rl, rg, acc);
    }

    for (int i = i0; i < n_steps; i += TW) {
        int inext = i + TW;
        bool has_next = (inext < n_steps);
        const float* xwrN = xw + (size_t)inext * L;
        const int* xirN = xi + (size_t)inext * L;

        // ---- reduce acc -> xe_w (sum over rg groups) ----
#pragma unroll
        for (int u = 0; u < 8; u++) {
            acc[u] += __shfl_xor_sync(0xffffffffu, acc[u], 8);
            acc[u] += __shfl_xor_sync(0xffffffffu, acc[u], 16);
        }
        if (rg == 0) {
#pragma unroll
            for (int u = 0; u < 8; u++) xe_w[rl * 8 + u] = acc[u];
        }
        __syncwarp();
#pragma unroll
        for (int u = 0; u < 8; u++) acc[u] = 0.f;

        // ---- dep(i): last j<i writing node tree[i,0] ----
        int v = tree[2 * i];
        int c = g_cnt[v];
        int d = -1;
        if (c <= SLOTS) {
            if (l < c) {
                int j = g_buck[v * SLOTS + l];
                if (j < i) d = j;
            }
        } else {
            if (l == 0)
                for (int j = i - 1; j >= 0; --j)
                    if (g_wr[j] == v) { d = j; break; }
        }
        d = __reduce_max_sync(0xffffffffu, d);

        // ---- W matvecs (pre-wait): a = W xe + b ----
        float4 wzrA = make_float4(bz2.x, bz2.y, br2.x, br2.y);
        float4 wzrB = make_float4(0.f, 0.f, 0.f, 0.f);
        float2 whA = bh2, whB = make_float2(0.f, 0.f);
#pragma unroll
        for (int k = 0; k < 64; k += 2) {
            float2 x = *reinterpret_cast<const float2*>(&xe_w[k]);
            float4 m0 = Wzr4[k * 32 + l];
            float4 m1 = Wzr4[(k + 1) * 32 + l];
            wzrA.x = fmaf(m0.x, x.x, wzrA.x); wzrA.y = fmaf(m0.y, x.x, wzrA.y);
            wzrA.z = fmaf(m0.z, x.x, wzrA.z); wzrA.w = fmaf(m0.w, x.x, wzrA.w);
            wzrB.x = fmaf(m1.x, x.y, wzrB.x); wzrB.y = fmaf(m1.y, x.y, wzrB.y);
            wzrB.z = fmaf(m1.z, x.y, wzrB.z); wzrB.w = fmaf(m1.w, x.y, wzrB.w);
            float4 mh = Wh4[(k >> 1) * 32 + l];
            whA.x = fmaf(mh.x, x.x, whA.x); whA.y = fmaf(mh.y, x.x, whA.y);
            whB.x = fmaf(mh.z, x.y, whB.x); whB.y = fmaf(mh.w, x.y, whB.y);
        }
        float2 az2 = make_float2(wzrA.x + wzrB.x, wzrA.y + wzrB.y);
        float2 ar2 = make_float2(wzrA.z + wzrB.z, wzrA.w + wzrB.w);
        float2 ah2 = make_float2(whA.x + whB.x, whA.y + whB.y);

        // ---- probe dep; gather next step's chunks while not ready ----
        int pr_r0 = 0;
        float2 p2;
        if (d >= 0) {
            int rdy = (l == 0) ? g_ready[d] : 0;
            rdy = __shfl_sync(0xffffffffu, rdy, 0);
            while (!rdy) {
                if (has_next && pr_r0 < L) {
                    gather_chunk(xwrN, xirN, pr_r0, rl, rg, acc);
                    pr_r0 += GCH;
                } else {
                    if (l == 0) {
                        int cnt = 0;
                        while (g_ready[d] == 0)
                            if (((++cnt) & 31) == 0) __nanosleep(64);
                    }
                    break;
                }
                rdy = (l == 0) ? g_ready[d] : 0;
                rdy = __shfl_sync(0xffffffffu, rdy, 0);
            }
            __syncwarp();
            __threadfence();   // acquire: order p load after flag observation
            p2 = __ldcg(reinterpret_cast<const float2*>(g_h + (size_t)d * HD) + l);
        } else {
            p2 = make_float2(0.f, 0.f);
        }
        *reinterpret_cast<float2*>(&p_w[2 * l]) = p2;
        __syncwarp();

        // ---- U z/r matvec ----
        float4 sA = make_float4(az2.x, az2.y, ar2.x, ar2.y);
        float4 sB = make_float4(0.f, 0.f, 0.f, 0.f);
#pragma unroll
        for (int k = 0; k < 64; k += 2) {
            float2 x = *reinterpret_cast<const float2*>(&p_w[k]);
            float4 m0 = Uzr4[k * 32 + l];
            float4 m1 = Uzr4[(k + 1) * 32 + l];
            sA.x = fmaf(m0.x, x.x, sA.x); sA.y = fmaf(m0.y, x.x, sA.y);
            sA.z = fmaf(m0.z, x.x, sA.z); sA.w = fmaf(m0.w, x.x, sA.w);
            sB.x = fmaf(m1.x, x.y, sB.x); sB.y = fmaf(m1.y, x.y, sB.y);
            sB.z = fmaf(m1.z, x.y, sB.z); sB.w = fmaf(m1.w, x.y, sB.w);
        }
        float2 z2, r2;
        z2.x = fminf(fmaxf(0.2f * (sA.x + sB.x) + 0.5f, 0.f), 1.f);
        z2.y = fminf(fmaxf(0.2f * (sA.y + sB.y) + 0.5f, 0.f), 1.f);
        r2.x = fminf(fmaxf(0.2f * (sA.z + sB.z) + 0.5f, 0.f), 1.f);
        r2.y = fminf(fmaxf(0.2f * (sA.w + sB.w) + 0.5f, 0.f), 1.f);
        *reinterpret_cast<float2*>(&pr_w[2 * l]) =
            make_float2(p2.x * r2.x, p2.y * r2.y);
        __syncwarp();

        // ---- Uh matvec ----
        float2 hA = ah2, hB = make_float2(0.f, 0.f);
#pragma unroll
        for (int kp = 0; kp < 32; kp++) {
            float2 x = *reinterpret_cast<const float2*>(&pr_w[2 * kp]);
            float4 m = Uh4[kp * 32 + l];
            hA.x = fmaf(m.x, x.x, hA.x); hA.y = fmaf(m.y, x.x, hA.y);
            hB.x = fmaf(m.z, x.y, hB.x); hB.y = fmaf(m.w, x.y, hB.y);
        }
        float2 h2;
        h2.x = z2.x * p2.x + (1.f - z2.x) * tanhf(hA.x + hB.x);
        h2.y = z2.y * p2.y + (1.f - z2.y) * tanhf(hA.y + hB.y);

        __stcg(reinterpret_cast<float2*>(g_h + (size_t)i * HD) + l, h2);
        if (i >= np1) {
            lm.x = fmaxf(lm.x, h2.x);
            lm.y = fmaxf(lm.y, h2.y);
        }
        __threadfence();          // release h stores
        __syncwarp();
        if (l == 0) g_ready[i] = 1;

        // ---- finish remaining gather chunks for next step ----
        while (has_next && pr_r0 < L) {
            gather_chunk(xwrN, xirN, pr_r0, rl, rg, acc);
            pr_r0 += GCH;
        }
    }

    // fold local max, then last block writes output
    unsigned ux = __float_as_uint(lm.x);
    ux = (ux & 0x80000000u) ? ~ux : (ux | 0x80000000u);
    unsigned uy = __float_as_uint(lm.y);
    uy = (uy & 0x80000000u) ? ~uy : (uy | 0x80000000u);
    atomicMax(&g_max[2 * l], ux);
    atomicMax(&g_max[2 * l + 1], uy);
    __threadfence();
    __syncthreads();
    __shared__ unsigned s_last;
    if (tid == 0) s_last = (atomicAdd(&g_done, 1u) == BLKS - 1) ? 1u : 0u;
    __syncthreads();
    if (s_last && tid < HD) {
        unsigned u = atomicMax(&g_max[tid], 0u);   // atomic read of final value
        unsigned b = (u & 0x80000000u) ? (u & 0x7fffffffu) : ~u;
        out[tid] = __uint_as_float(b);
    }
}

// ---------------- launch ----------------
extern "C" void kernel_launch(void* const* d_in, const int* in_sizes, int n_in,
                              void* d_out, int out_size) {
    const float* xw = (const float*)d_in[0];
    const int* xi = (const int*)d_in[1];
    const int* tree = (const int*)d_in[2];
    const int* np = (const int*)d_in[3];
    const float* emb = (const float*)d_in[4];
    const float* Wz = (const float*)d_in[5];
    const float* Uz = (const float*)d_in[6];
    const float* bz = (const float*)d_in[7];
    const float* Wr = (const float*)d_in[8];
    const float* Ur = (const float*)d_in[9];
    const float* br = (const float*)d_in[10];
    const float* Wh = (const float*)d_in[11];
    const float* Uh = (const float*)d_in[12];
    const float* bh = (const float*)d_in[13];

    int N = in_sizes[2] / 2;      // tree is [N,2]
    int L = in_sizes[0] / N;      // x_word is [N,L]
    int n_steps = N - 1;
    int emb_total = in_sizes[4];  // V*H floats

    static int smem_set = 0;
    const int SMEM_BYTES = (24576 + 1536) * 4;  // 104448
    if (!smem_set) {
        cudaFuncSetAttribute(fused_kernel,
                             cudaFuncAttributeMaxDynamicSharedMemorySize, SMEM_BYTES);
        smem_set = 1;
    }

    int prep_threads = (emb_total + 3) / 4;
    if (prep_threads < MAXN) prep_threads = MAXN;
    prep_kernel<<<(prep_threads + 255) / 256, 256>>>(emb, tree, n_steps, emb_total);
    fill_kernel<<<(n_steps + 255) / 256, 256>>>(tree, n_steps);
    fused_kernel<<<BLKS, 256, SMEM_BYTES>>>(xw, xi, tree, Wz, Uz, bz, Wr, Ur, br,
                                            Wh, Uh, bh, np, L, n_steps,
                                            (float*)d_out);
}